// round 5
// baseline (speedup 1.0000x reference)
#include <cuda_runtime.h>
#include <cuda_fp16.h>

#define Bb 32
#define Nn 512
#define Mm 512
#define KD 64
#define SPAD 1024             // padded s-extent per row (s = i'+j' in [0,1022])
#define BIGV 1e10f
#define LOG2E 1.44269504088896340736f
#define LN2   0.69314718055994530942f

// Skewed cost matrix, base-2 units: g_D[b][i'][s] = log2(e)*D[b][i'][s-i']
// fp16: 32*512*1024*2B = 33.5 MB (L2-resident producer->consumer handoff)
__device__ __half g_D[(size_t)Bb * Nn * SPAD];

__device__ __forceinline__ float ex2f(float x) {
    float r; asm("ex2.approx.f32 %0, %1;" : "=f"(r) : "f"(x)); return r;
}
__device__ __forceinline__ float lg2f(float x) {
    float r; asm("lg2.approx.f32 %0, %1;" : "=f"(r) : "f"(x)); return r;
}

struct Pack8 { __half h[8]; };

// ---------------------------------------------------------------------------
// Kernel 1: cost matrix via Gram trick. X tile row-major (broadcast loads),
// Y tile transposed (conflict-free float4 loads). 16 FFMA / 16 cells / k.
// ---------------------------------------------------------------------------
__global__ __launch_bounds__(256) void cost_kernel(const float* __restrict__ X,
                                                   const float* __restrict__ Y,
                                                   const int* __restrict__ Xl,
                                                   const int* __restrict__ Yl) {
    const int I0 = blockIdx.x * 64;
    const int J0 = blockIdx.y * 64;
    const int b  = blockIdx.z;
    if (I0 >= Xl[b] || J0 >= Yl[b]) return;   // dead tile

    __shared__ float Xs[64 * 68];   // Xs[row][k], pitch 68
    __shared__ float Yt[64 * 68];   // Yt[k][j],  pitch 68 (transposed)
    __shared__ float xn[64], yn[64];

    const int tid = threadIdx.x;
    {
        int lr = tid >> 4;
        int lc = (tid & 15) * 4;
        #pragma unroll
        for (int rr = 0; rr < 64; rr += 16) {
            float4 vx = *(const float4*)&X[((size_t)(b * Nn + I0 + lr + rr)) * KD + lc];
            *(float4*)&Xs[(lr + rr) * 68 + lc] = vx;
            float4 vy = *(const float4*)&Y[((size_t)(b * Mm + J0 + lr + rr)) * KD + lc];
            Yt[(lc + 0) * 68 + lr + rr] = vy.x;
            Yt[(lc + 1) * 68 + lr + rr] = vy.y;
            Yt[(lc + 2) * 68 + lr + rr] = vy.z;
            Yt[(lc + 3) * 68 + lr + rr] = vy.w;
        }
    }
    __syncthreads();

    // row norms (cooperative, cheap)
    if (tid < 128) {
        int i = tid & 63;
        float s = 0.f;
        if (tid < 64) {
            #pragma unroll 8
            for (int k = 0; k < 64; k++) { float v = Xs[i * 68 + k]; s = fmaf(v, v, s); }
            xn[i] = s;
        } else {
            #pragma unroll 8
            for (int k = 0; k < 64; k++) { float v = Yt[k * 68 + i]; s = fmaf(v, v, s); }
            yn[i] = s;
        }
    }
    __syncthreads();

    const int ty4 = (tid >> 4) * 4;
    const int tx4 = (tid & 15) * 4;
    float acc[4][4];
    #pragma unroll
    for (int r = 0; r < 4; r++)
        #pragma unroll
        for (int c = 0; c < 4; c++) acc[r][c] = 0.f;

    #pragma unroll 4
    for (int k = 0; k < KD; k++) {
        float a0 = Xs[(ty4 + 0) * 68 + k];
        float a1 = Xs[(ty4 + 1) * 68 + k];
        float a2 = Xs[(ty4 + 2) * 68 + k];
        float a3 = Xs[(ty4 + 3) * 68 + k];
        float4 bv = *(const float4*)&Yt[k * 68 + tx4];
        acc[0][0] = fmaf(a0, bv.x, acc[0][0]); acc[0][1] = fmaf(a0, bv.y, acc[0][1]);
        acc[0][2] = fmaf(a0, bv.z, acc[0][2]); acc[0][3] = fmaf(a0, bv.w, acc[0][3]);
        acc[1][0] = fmaf(a1, bv.x, acc[1][0]); acc[1][1] = fmaf(a1, bv.y, acc[1][1]);
        acc[1][2] = fmaf(a1, bv.z, acc[1][2]); acc[1][3] = fmaf(a1, bv.w, acc[1][3]);
        acc[2][0] = fmaf(a2, bv.x, acc[2][0]); acc[2][1] = fmaf(a2, bv.y, acc[2][1]);
        acc[2][2] = fmaf(a2, bv.z, acc[2][2]); acc[2][3] = fmaf(a2, bv.w, acc[2][3]);
        acc[3][0] = fmaf(a3, bv.x, acc[3][0]); acc[3][1] = fmaf(a3, bv.y, acc[3][1]);
        acc[3][2] = fmaf(a3, bv.z, acc[3][2]); acc[3][3] = fmaf(a3, bv.w, acc[3][3]);
    }

    float y0 = yn[tx4 + 0], y1 = yn[tx4 + 1], y2 = yn[tx4 + 2], y3 = yn[tx4 + 3];
    #pragma unroll
    for (int r = 0; r < 4; r++) {
        int gi = I0 + ty4 + r;
        float xr = xn[ty4 + r];
        __half* dst = g_D + ((size_t)(b * Nn + gi)) * SPAD + (gi + J0 + tx4);
        dst[0] = __float2half(LOG2E * (xr + y0 - 2.f * acc[r][0]));
        dst[1] = __float2half(LOG2E * (xr + y1 - 2.f * acc[r][1]));
        dst[2] = __float2half(LOG2E * (xr + y2 - 2.f * acc[r][2]));
        dst[3] = __float2half(LOG2E * (xr + y3 - 2.f * acc[r][3]));
    }
}

// ---------------------------------------------------------------------------
// Kernel 2: wavefront DP, 4 rows/thread, 128 threads (4 warps) per batch.
// Thread t owns rows i = 4t+1 .. 4t+4. Values indexed (row, diagonal):
//   v1[r] = R[row, d-1], v2[r] = R[row, d-2] in registers
//   bnd1/bnd2 = neighbor's bottom row (4t) at d-1 / d-2
// Only one cross-thread value per diagonal: shfl in-warp, smem cross-warp.
// ---------------------------------------------------------------------------
__global__ __launch_bounds__(128) void dp_kernel(const int* __restrict__ Xl,
                                                 const int* __restrict__ Yl,
                                                 float* __restrict__ out) {
    __shared__ float xch[2][4];     // [diag parity][warp]

    const int b    = blockIdx.x;
    const int t    = threadIdx.x;   // 0..127
    const int w    = t >> 5;
    const int lane = t & 31;
    const int i0   = 4 * t + 1;     // first owned row (1-based)

    const int it = Xl[b];
    const int jt = Yl[b];
    const int td = it + jt;

    const int  wlo    = 128 * w + 1;                 // warp's first row
    const int  wdhi   = min(128 * w + 128, it) + jt; // last live diagonal
    const bool wrowok = (wlo <= it);

    const int tout = (it - 1) >> 2;
    const int rout = (it - 1) & 3;

    const __half* Dbase = g_D + ((size_t)b * Nn + (i0 - 1)) * SPAD;
    const int4* Dr0 = (const int4*)(Dbase);
    const int4* Dr1 = (const int4*)(Dbase + SPAD);
    const int4* Dr2 = (const int4*)(Dbase + 2 * SPAD);
    const int4* Dr3 = (const int4*)(Dbase + 3 * SPAD);

    int4 cur0 = Dr0[0], cur1 = Dr1[0], cur2 = Dr2[0], cur3 = Dr3[0];
    int4 nxt0 = Dr0[1], nxt1 = Dr1[1], nxt2 = Dr2[1], nxt3 = Dr3[1];

    float v1[4], v2[4];
    #pragma unroll
    for (int r = 0; r < 4; r++) { v1[r] = BIGV; v2[r] = BIGV; }
    float bnd1 = BIGV;                    // R[i0-1, d-1]
    float bnd2 = (t == 0) ? 0.f : BIGV;   // R[i0-1, d-2]; R[0,0]=0 for d=2

    for (int dbase = 2; dbase <= td; dbase += 8) {
        int pn = min(((dbase - 2) >> 3) + 2, SPAD / 8 - 1);
        int4 pf0 = Dr0[pn], pf1 = Dr1[pn], pf2 = Dr2[pn], pf3 = Dr3[pn];

        #pragma unroll
        for (int u = 0; u < 8; ++u) {
            const int d = dbase + u;
            if (d > td) break;            // CTA-uniform

            float nv[4];
            const bool warp_live = wrowok && (d > wlo) && (d <= wdhi);
            if (warp_live) {
                #pragma unroll
                for (int r = 0; r < 4; r++) {
                    float a  = (r == 0) ? bnd2 : v2[r - 1];   // R[i-1, d-2]
                    float bb = (r == 0) ? bnd1 : v1[r - 1];   // R[i-1, d-1]
                    float c  = v1[r];                          // R[i,   d-1]
                    float m  = fminf(a, fminf(bb, c));
                    float da = m - a, db = m - bb, dc = m - c; // one is 0
                    bool isa = (m == a), isb = (m == bb);
                    float t1 = isa ? db : da;
                    float t2 = isa ? dc : (isb ? dc : db);
                    float soft = m - lg2f(1.0f + ex2f(t1) + ex2f(t2));
                    const int gi = i0 + r;
                    bool live = (gi <= it) && (d > gi) && (d <= gi + jt);
                    __half hD = (r == 0) ? ((const Pack8&)cur0).h[u]
                              : (r == 1) ? ((const Pack8&)cur1).h[u]
                              : (r == 2) ? ((const Pack8&)cur2).h[u]
                                         : ((const Pack8&)cur3).h[u];
                    nv[r] = live ? (__half2float(hD) + soft) : BIGV;
                }
            } else {
                nv[0] = nv[1] = nv[2] = nv[3] = BIGV;
            }

            if (d == td && t == tout) {
                float ov = (rout == 0) ? nv[0] : (rout == 1) ? nv[1]
                         : (rout == 2) ? nv[2] : nv[3];
                out[b] = ov * LN2;
            }

            // pass bottom row (i0+3 = 4t+4) to the next thread
            float up = __shfl_up_sync(0xffffffffu, nv[3], 1);
            if (lane == 31) xch[d & 1][w] = nv[3];
            __syncthreads();
            float nb = (lane == 0) ? ((w == 0) ? BIGV : xch[d & 1][w - 1]) : up;

            v2[0] = v1[0]; v2[1] = v1[1]; v2[2] = v1[2]; v2[3] = v1[3];
            v1[0] = nv[0]; v1[1] = nv[1]; v1[2] = nv[2]; v1[3] = nv[3];
            bnd2 = bnd1;
            bnd1 = nb;
        }
        cur0 = nxt0; cur1 = nxt1; cur2 = nxt2; cur3 = nxt3;
        nxt0 = pf0;  nxt1 = pf1;  nxt2 = pf2;  nxt3 = pf3;
    }
}

// ---------------------------------------------------------------------------
extern "C" void kernel_launch(void* const* d_in, const int* in_sizes, int n_in,
                              void* d_out, int out_size) {
    const float* X  = (const float*)d_in[0];
    const float* Y  = (const float*)d_in[1];
    const int*   Xl = (const int*)d_in[2];
    const int*   Yl = (const int*)d_in[3];
    float* out = (float*)d_out;

    dim3 gcost(Nn / 64, Mm / 64, Bb);
    cost_kernel<<<gcost, 256>>>(X, Y, Xl, Yl);
    dp_kernel<<<Bb, 128>>>(Xl, Yl, out);
}

// round 9
// speedup vs baseline: 2.0252x; 2.0252x over previous
#include <cuda_runtime.h>
#include <cuda_fp16.h>

#define Bb 32
#define Nn 512
#define Mm 512
#define KD 64
#define SPAD 1024             // padded s-extent per row (s = i'+j' in [0,1022])
#define BIGV 1e10f
#define LOG2E 1.44269504088896340736f
#define LN2   0.69314718055994530942f

#define NW 8                  // warps per CTA (dp)
#define CHUNK 32              // diagonals per handshake chunk
#define BND_LEN 1056
#define NCHUNK 40

// Skewed cost matrix, base-2 units: g_D[b][i'][s] = log2(e)*D[b][i'][s-i']
__device__ __half g_D[(size_t)Bb * Nn * SPAD];

__device__ __forceinline__ float ex2f(float x) {
    float r; asm("ex2.approx.f32 %0, %1;" : "=f"(r) : "f"(x)); return r;
}
__device__ __forceinline__ float lg2f(float x) {
    float r; asm("lg2.approx.f32 %0, %1;" : "=f"(r) : "f"(x)); return r;
}

struct Pack8 { __half h[8]; };

// ---------------------------------------------------------------------------
// Kernel 1: cost matrix via Gram trick (unchanged from R5).
// ---------------------------------------------------------------------------
__global__ __launch_bounds__(256) void cost_kernel(const float* __restrict__ X,
                                                   const float* __restrict__ Y,
                                                   const int* __restrict__ Xl,
                                                   const int* __restrict__ Yl) {
    const int I0 = blockIdx.x * 64;
    const int J0 = blockIdx.y * 64;
    const int b  = blockIdx.z;
    if (I0 >= Xl[b] || J0 >= Yl[b]) return;

    __shared__ float Xs[64 * 68];
    __shared__ float Yt[64 * 68];
    __shared__ float xn[64], yn[64];

    const int tid = threadIdx.x;
    {
        int lr = tid >> 4;
        int lc = (tid & 15) * 4;
        #pragma unroll
        for (int rr = 0; rr < 64; rr += 16) {
            float4 vx = *(const float4*)&X[((size_t)(b * Nn + I0 + lr + rr)) * KD + lc];
            *(float4*)&Xs[(lr + rr) * 68 + lc] = vx;
            float4 vy = *(const float4*)&Y[((size_t)(b * Mm + J0 + lr + rr)) * KD + lc];
            Yt[(lc + 0) * 68 + lr + rr] = vy.x;
            Yt[(lc + 1) * 68 + lr + rr] = vy.y;
            Yt[(lc + 2) * 68 + lr + rr] = vy.z;
            Yt[(lc + 3) * 68 + lr + rr] = vy.w;
        }
    }
    __syncthreads();

    if (tid < 128) {
        int i = tid & 63;
        float s = 0.f;
        if (tid < 64) {
            #pragma unroll 8
            for (int k = 0; k < 64; k++) { float v = Xs[i * 68 + k]; s = fmaf(v, v, s); }
            xn[i] = s;
        } else {
            #pragma unroll 8
            for (int k = 0; k < 64; k++) { float v = Yt[k * 68 + i]; s = fmaf(v, v, s); }
            yn[i] = s;
        }
    }
    __syncthreads();

    const int ty4 = (tid >> 4) * 4;
    const int tx4 = (tid & 15) * 4;
    float acc[4][4];
    #pragma unroll
    for (int r = 0; r < 4; r++)
        #pragma unroll
        for (int c = 0; c < 4; c++) acc[r][c] = 0.f;

    #pragma unroll 4
    for (int k = 0; k < KD; k++) {
        float a0 = Xs[(ty4 + 0) * 68 + k];
        float a1 = Xs[(ty4 + 1) * 68 + k];
        float a2 = Xs[(ty4 + 2) * 68 + k];
        float a3 = Xs[(ty4 + 3) * 68 + k];
        float4 bv = *(const float4*)&Yt[k * 68 + tx4];
        acc[0][0] = fmaf(a0, bv.x, acc[0][0]); acc[0][1] = fmaf(a0, bv.y, acc[0][1]);
        acc[0][2] = fmaf(a0, bv.z, acc[0][2]); acc[0][3] = fmaf(a0, bv.w, acc[0][3]);
        acc[1][0] = fmaf(a1, bv.x, acc[1][0]); acc[1][1] = fmaf(a1, bv.y, acc[1][1]);
        acc[1][2] = fmaf(a1, bv.z, acc[1][2]); acc[1][3] = fmaf(a1, bv.w, acc[1][3]);
        acc[2][0] = fmaf(a2, bv.x, acc[2][0]); acc[2][1] = fmaf(a2, bv.y, acc[2][1]);
        acc[2][2] = fmaf(a2, bv.z, acc[2][2]); acc[2][3] = fmaf(a2, bv.w, acc[2][3]);
        acc[3][0] = fmaf(a3, bv.x, acc[3][0]); acc[3][1] = fmaf(a3, bv.y, acc[3][1]);
        acc[3][2] = fmaf(a3, bv.z, acc[3][2]); acc[3][3] = fmaf(a3, bv.w, acc[3][3]);
    }

    float y0 = yn[tx4 + 0], y1 = yn[tx4 + 1], y2 = yn[tx4 + 2], y3 = yn[tx4 + 3];
    #pragma unroll
    for (int r = 0; r < 4; r++) {
        int gi = I0 + ty4 + r;
        float xr = xn[ty4 + r];
        __half* dst = g_D + ((size_t)(b * Nn + gi)) * SPAD + (gi + J0 + tx4);
        dst[0] = __float2half(LOG2E * (xr + y0 - 2.f * acc[r][0]));
        dst[1] = __float2half(LOG2E * (xr + y1 - 2.f * acc[r][1]));
        dst[2] = __float2half(LOG2E * (xr + y2 - 2.f * acc[r][2]));
        dst[3] = __float2half(LOG2E * (xr + y3 - 2.f * acc[r][3]));
    }
}

// ---------------------------------------------------------------------------
// Kernel 2: barrier-free pipelined wavefront.
// Warp w owns rows [64w+1, 64w+64]; lane l owns rows i1=64w+2l+1, i2=i1+1.
// Chunk c covers diagonals d in [32c+2, 32c+33]. Warp w publishes its bottom
// row (64w+64) values into bndM[w+1][d] and flags chunk completion; warp w+1
// spin-polls the flag. Warp 0 reads a pre-filled BIG boundary (row 0).
// ---------------------------------------------------------------------------
__global__ __launch_bounds__(NW * 32) void dp_kernel(const int* __restrict__ Xl,
                                                     const int* __restrict__ Yl,
                                                     float* __restrict__ out) {
    __shared__ float bndM[NW][BND_LEN];   // bndM[w][d] = R(64w, d)
    __shared__ int   flagsA[NW - 1][NCHUNK];

    const int b    = blockIdx.x;
    const int t    = threadIdx.x;
    const int w    = t >> 5;
    const int lane = t & 31;

    // init: boundary row 0 = BIG everywhere (R[0,0]=0 handled by register seed)
    for (int idx = t; idx < BND_LEN; idx += NW * 32) bndM[0][idx] = BIGV;
    for (int idx = t; idx < (NW - 1) * NCHUNK; idx += NW * 32)
        ((int*)flagsA)[idx] = 0;
    __syncthreads();

    const int it = Xl[b];
    const int jt = Yl[b];
    const int td = it + jt;
    const int c_end = (td - 2) >> 5;

    const int i1 = 64 * w + 2 * lane + 1;
    const int i2 = i1 + 1;

    const bool warp_dead = (64 * w + 1 > it);
    const int c_lo = warp_dead ? (c_end + 1) : ((w > 0) ? (2 * w - 1) : 0);
    const int c_hi = warp_dead ? c_end
                   : min((min(64 * w + 64, it) + jt - 2) >> 5, c_end);

    const int  dlo1 = i1 + 1, dhi1 = (i1 <= it) ? (i1 + jt) : 0;
    const int  dlo2 = i2 + 1, dhi2 = (i2 <= it) ? (i2 + jt) : 0;
    const bool io1 = (i1 == it), io2 = (i2 == it);

    const int4* DrowA = (const int4*)(g_D + ((size_t)b * Nn + (i1 - 1)) * SPAD);
    const int4* DrowB = (const int4*)(g_D + ((size_t)b * Nn + (i2 - 1)) * SPAD);

    // ---- fast phase 1: dead chunks before the live window ----
    for (int c = 0; c < c_lo && c <= c_end; ++c) {
        if (w < NW - 1) {
            bndM[w + 1][32 * c + 2 + lane] = BIGV;
            __syncwarp();
            __threadfence_block();
            if (lane == 0) *(volatile int*)&flagsA[w][c] = 1;
        }
    }

    // ---- slow phase: live window ----
    float up1 = BIGV;                       // R(i1-1, d-1)
    float up2 = (t == 0) ? 0.f : BIGV;      // R(i1-1, d-2); seed R[0,0]=0
    float v1a = BIGV, v1b = BIGV, v2a = BIGV;
    float outv = 0.f;

    int q0 = min(4 * c_lo, 126);
    int4 curA = DrowA[q0], nxtA = DrowA[q0 + 1];
    int4 curB = DrowB[q0], nxtB = DrowB[q0 + 1];

    for (int c = c_lo; c <= c_hi; ++c) {
        if (w > 0) {
            volatile int* f = (volatile int*)&flagsA[w - 1][c];
            while (*f == 0) {}
            __threadfence_block();
        }
        const int dbase = 32 * c + 2;
        #pragma unroll
        for (int blk = 0; blk < 4; ++blk) {
            int qn = min(4 * c + blk + 2, 127);
            int4 pfA = DrowA[qn], pfB = DrowB[qn];
            Pack8 pa = (Pack8&)curA, pb = (Pack8&)curB;
            #pragma unroll
            for (int u = 0; u < 8; ++u) {
                const int d = dbase + blk * 8 + u;
                // cell 1 (row i1): a=up2, b=up1, c=v1a
                float m1 = fminf(up2, fminf(up1, v1a));
                float x1 = (m1 == up2) ? (m1 - up1) : (m1 - up2);
                float y1 = (m1 == up2) ? (m1 - v1a)
                                       : ((m1 == up1) ? (m1 - v1a) : (m1 - up1));
                float s1 = m1 - lg2f(1.f + ex2f(x1) + ex2f(y1));
                bool  l1 = (d >= dlo1) && (d <= dhi1);
                float nv1 = l1 ? (__half2float(pa.h[u]) + s1) : BIGV;
                // cell 2 (row i2): a=v2a, b=v1a, c=v1b
                float m2 = fminf(v2a, fminf(v1a, v1b));
                float x2 = (m2 == v2a) ? (m2 - v1a) : (m2 - v2a);
                float y2 = (m2 == v2a) ? (m2 - v1b)
                                       : ((m2 == v1a) ? (m2 - v1b) : (m2 - v1a));
                float s2 = m2 - lg2f(1.f + ex2f(x2) + ex2f(y2));
                bool  l2 = (d >= dlo2) && (d <= dhi2);
                float nv2 = l2 ? (__half2float(pb.h[u]) + s2) : BIGV;
                // output capture
                if (d == td) outv = io1 ? nv1 : (io2 ? nv2 : outv);
                // publish bottom row to next strip
                if (w < NW - 1 && lane == 31) bndM[w + 1][d] = nv2;
                // next-step neighbor values
                float sh = __shfl_up_sync(0xffffffffu, nv2, 1);
                float bv = bndM[w][d];
                up2 = up1;
                up1 = (lane == 0) ? bv : sh;
                v2a = v1a; v1a = nv1; v1b = nv2;
            }
            curA = nxtA; nxtA = pfA;
            curB = nxtB; nxtB = pfB;
        }
        if (w < NW - 1) {
            __syncwarp();
            __threadfence_block();
            if (lane == 0) *(volatile int*)&flagsA[w][c] = 1;
        }
    }

    // ---- fast phase 2: dead chunks after the live window ----
    for (int c = c_hi + 1; c <= c_end; ++c) {
        if (w < NW - 1) {
            bndM[w + 1][32 * c + 2 + lane] = BIGV;
            __syncwarp();
            __threadfence_block();
            if (lane == 0) *(volatile int*)&flagsA[w][c] = 1;
        }
    }

    if (io1 || io2) out[b] = outv * LN2;
}

// ---------------------------------------------------------------------------
extern "C" void kernel_launch(void* const* d_in, const int* in_sizes, int n_in,
                              void* d_out, int out_size) {
    const float* X  = (const float*)d_in[0];
    const float* Y  = (const float*)d_in[1];
    const int*   Xl = (const int*)d_in[2];
    const int*   Yl = (const int*)d_in[3];
    float* out = (float*)d_out;

    dim3 gcost(Nn / 64, Mm / 64, Bb);
    cost_kernel<<<gcost, 256>>>(X, Y, Xl, Yl);
    dp_kernel<<<Bb, NW * 32>>>(Xl, Yl, out);
}